// round 5
// baseline (speedup 1.0000x reference)
#include <cuda_runtime.h>
#include <cuda_bf16.h>
#include <cstdint>

// Problem constants (PairInitOPM: B=1, L=768, sd=384, pd=128)
#define Lq 768
#define SD 384
#define PD 128
#define SD4 (SD / 4)   // 96
#define PD4 (PD / 4)   // 32

// Scratch (allocation-free rule: __device__ globals)
__device__ float g_P[Lq * PD];            // si  (includes bi)
__device__ float g_Q[Lq * PD];            // sj  (includes bj)
__device__ float g_U[Lq * PD];            // zi + bm
__device__ float g_V[Lq * PD];            // zj
__device__ float4 g_Wt4[SD4 * 256];       // Wt4[kb][c] = W[c][4kb..4kb+3], W = [wi;wj]
__device__ float4 g_WmT4[PD4 * 256];      // WmT4[kb][c] = wm[c&127][(c>>7)*128 + 4kb..]

// ---- packed f32x2 helpers (FFMA2: 2 fp32 FMA per instruction) ----
__device__ __forceinline__ uint64_t pk2(float lo, float hi) {
    uint64_t r; asm("mov.b64 %0, {%1, %2};" : "=l"(r) : "f"(lo), "f"(hi)); return r;
}
__device__ __forceinline__ void upk2(uint64_t v, float& lo, float& hi) {
    asm("mov.b64 {%0, %1}, %2;" : "=f"(lo), "=f"(hi) : "l"(v));
}
__device__ __forceinline__ uint64_t fma2(uint64_t a, uint64_t b, uint64_t c) {
    uint64_t d; asm("fma.rn.f32x2 %0, %1, %2, %3;" : "=l"(d) : "l"(a), "l"(b), "l"(c));
    return d;
}

// ---------------------------------------------------------------------------
// Kernel 0: weight transpose (tiny). 128 blocks x 256.
// ---------------------------------------------------------------------------
__global__ __launch_bounds__(256) void k0_transpose(
    const float* __restrict__ wi, const float* __restrict__ wj,
    const float* __restrict__ wm)
{
    int idx = blockIdx.x * 256 + threadIdx.x;
    if (idx < SD4 * 256) {
        int kb = idx >> 8, c = idx & 255;
        const float4* wr4 = (const float4*)((c < PD) ? (wi + c * SD)
                                                     : (wj + (c - PD) * SD));
        g_Wt4[kb * 256 + c] = wr4[kb];
    } else if (idx < (SD4 + PD4) * 256) {
        int j = idx - SD4 * 256;
        int kb = j >> 8, c = j & 255;
        const float4* wr4 = (const float4*)(wm + (c & 127) * (2 * PD) + (c >> 7) * PD);
        g_WmT4[kb * 256 + c] = wr4[kb];
    }
}

// ---------------------------------------------------------------------------
// Kernel 1: TI=6 rows/block -> 128 blocks = one wave.
// Weights: coalesced LDG.128 from transposed layout (no weight SMEM at all).
// s / sisj: LDS.128 broadcast. FMAs: packed f32x2.
// ---------------------------------------------------------------------------
#define TI 6

__global__ __launch_bounds__(256) void k1_proj(
    const float* __restrict__ s,
    const float* __restrict__ bi, const float* __restrict__ bj,
    const float* __restrict__ bm)
{
    __shared__ float4 s_sh4[TI * SD4];   // 9.2 KB
    __shared__ float4 sisj4[TI * 64];    // 6 KB

    const int t  = threadIdx.x;          // output column c = t
    const int i0 = blockIdx.x * TI;

    const float4* __restrict__ S4 = (const float4*)s;
    for (int idx = t; idx < TI * SD4; idx += 256)
        s_sh4[idx] = S4[i0 * SD4 + idx];
    __syncthreads();

    // ---- Phase A: acc[r] = sum_k s[i0+r][k] * W[t][k] ----
    uint64_t acc2[TI];
#pragma unroll
    for (int r = 0; r < TI; r++) acc2[r] = 0ull;

#pragma unroll 4
    for (int kb = 0; kb < SD4; kb++) {
        float4 w4 = g_Wt4[kb * 256 + t];          // coalesced LDG.128 (L1/L2 hit)
        uint64_t wlo = pk2(w4.x, w4.y), whi = pk2(w4.z, w4.w);
#pragma unroll
        for (int r = 0; r < TI; r++) {
            float4 s4 = s_sh4[r * SD4 + kb];      // LDS.128 broadcast
            acc2[r] = fma2(pk2(s4.x, s4.y), wlo, acc2[r]);
            acc2[r] = fma2(pk2(s4.z, s4.w), whi, acc2[r]);
        }
    }

    float acc[TI];
    {
        float b = (t < PD) ? bi[t] : bj[t - PD];
#pragma unroll
        for (int r = 0; r < TI; r++) {
            float lo, hi; upk2(acc2[r], lo, hi);
            acc[r] = lo + hi + b;
        }
    }

    // Publish sisj [TI][256]
    float* sisj = (float*)sisj4;
#pragma unroll
    for (int r = 0; r < TI; r++) sisj[r * 256 + t] = acc[r];
    __syncthreads();

    // ---- Phase B: accz[e] = sum_d sisj[r][which*128+d] * wm[e][which*128+d] ----
    const int which = t >> 7;            // uniform per warp
    const int e     = t & 127;
    uint64_t az2[TI];
#pragma unroll
    for (int r = 0; r < TI; r++) az2[r] = 0ull;

#pragma unroll 4
    for (int kb = 0; kb < PD4; kb++) {
        float4 w4 = g_WmT4[kb * 256 + t];         // coalesced LDG.128
        uint64_t wlo = pk2(w4.x, w4.y), whi = pk2(w4.z, w4.w);
#pragma unroll
        for (int r = 0; r < TI; r++) {
            float4 z4 = sisj4[r * 64 + which * 32 + kb];   // LDS.128 broadcast
            az2[r] = fma2(pk2(z4.x, z4.y), wlo, az2[r]);
            az2[r] = fma2(pk2(z4.z, z4.w), whi, az2[r]);
        }
    }

    const float bmv = bm[e];
#pragma unroll
    for (int r = 0; r < TI; r++) {
        float lo, hi; upk2(az2[r], lo, hi);
        float z = lo + hi;
        int i = i0 + r;
        if (which == 0) {
            g_P[i * PD + e] = acc[r];
            g_U[i * PD + e] = z + bmv;
        } else {
            g_Q[i * PD + e] = acc[r];
            g_V[i * PD + e] = z;
        }
    }
}

// ---------------------------------------------------------------------------
// Kernel 2: z0[i,j,d] = U[i,d] + V[j,d] + P[i,d]*Q[j,d]
// Block = 8 i x 24 j tile (24 KB smem) at 8 blocks/SM for full occupancy.
// Streaming float4 stores.
// ---------------------------------------------------------------------------
#define BI 8
#define BJ 24

__global__ __launch_bounds__(256, 8) void k2_outer(float* __restrict__ out)
{
    __shared__ float4 q_sh[BJ * 32];   // 12 KB
    __shared__ float4 v_sh[BJ * 32];   // 12 KB

    const int t  = threadIdx.x;
    const int tx = t & 31;             // d quad: d = 4*tx
    const int ty = t >> 5;             // i within tile (0..7)
    const int i  = blockIdx.x * BI + ty;
    const int j0 = blockIdx.y * BJ;

    const float4* __restrict__ P4 = (const float4*)g_P;
    const float4* __restrict__ Q4 = (const float4*)g_Q;
    const float4* __restrict__ U4 = (const float4*)g_U;
    const float4* __restrict__ V4 = (const float4*)g_V;

#pragma unroll
    for (int m = 0; m < (BJ * 32) / 256; m++) {
        int idx = t + m * 256;
        q_sh[idx] = Q4[j0 * 32 + idx];
        v_sh[idx] = V4[j0 * 32 + idx];
    }

    const float4 p = P4[i * 32 + tx];
    const float4 u = U4[i * 32 + tx];
    __syncthreads();

    float4* out4 = (float4*)out;
    size_t base = ((size_t)i * Lq + j0) * 32 + tx;

#pragma unroll 4
    for (int jj = 0; jj < BJ; jj++) {
        float4 q = q_sh[jj * 32 + tx];     // LDS.128, conflict-free
        float4 v = v_sh[jj * 32 + tx];
        float4 o;
        o.x = fmaf(p.x, q.x, u.x + v.x);
        o.y = fmaf(p.y, q.y, u.y + v.y);
        o.z = fmaf(p.z, q.z, u.z + v.z);
        o.w = fmaf(p.w, q.w, u.w + v.w);
        __stcs(&out4[base + (size_t)jj * 32], o);  // streaming store
    }
}

// ---------------------------------------------------------------------------
extern "C" void kernel_launch(void* const* d_in, const int* in_sizes, int n_in,
                              void* d_out, int out_size)
{
    const float* s  = (const float*)d_in[0];
    const float* wi = (const float*)d_in[1];
    const float* bi = (const float*)d_in[2];
    const float* wj = (const float*)d_in[3];
    const float* bj = (const float*)d_in[4];
    const float* wm = (const float*)d_in[5];
    const float* bm = (const float*)d_in[6];
    float* out = (float*)d_out;

    k0_transpose<<<128, 256>>>(wi, wj, wm);
    k1_proj<<<Lq / TI, 256>>>(s, bi, bj, bm);

    dim3 grid2(Lq / BI, Lq / BJ);
    k2_outer<<<grid2, 256>>>(out);
}